// round 3
// baseline (speedup 1.0000x reference)
#include <cuda_runtime.h>

#define V0    32000
#define EDIM  1024
#define TSTEP 65
#define TPAD  66
#define R3    3072
#define VOUT  32002
#define GBLK  128     // persistent recurrence blocks (<=148 SMs -> co-resident)
#define HSW   70      // padded t-width in shared (even -> 8B-aligned rows)

typedef unsigned long long ull;

// ---------------- scratch (__device__ globals; no allocs allowed) ----------------
__device__ __align__(16) float g_a[320];
__device__ __align__(16) float g_c[EDIM];
__device__ __align__(16) float g_gib[R3];
__device__ __align__(16) float g_gi[TPAD * R3];     // gi[t][j], t=65 is pad
__device__ __align__(16) float g_h2[2][EDIM];       // double-buffered hidden state
__device__ __align__(16) float g_Hb[EDIM * TPAD];   // relu(h_t), layout [k][t], t=65 pad col = 0
__device__ unsigned int g_bar;

// ---------------- f32x2 helpers ----------------
__device__ __forceinline__ ull pk2(float x, float y) {
    ull r; asm("mov.b64 %0,{%1,%2};" : "=l"(r) : "f"(x), "f"(y)); return r;
}
__device__ __forceinline__ void upk2(ull p, float &x, float &y) {
    asm("mov.b64 {%0,%1},%2;" : "=f"(x), "=f"(y) : "l"(p));
}
__device__ __forceinline__ ull ffma2(ull a, ull b, ull c) {
    ull d; asm("fma.rn.f32x2 %0,%1,%2,%3;" : "=l"(d) : "l"(a), "l"(b), "l"(c)); return d;
}
__device__ __forceinline__ float sigf(float x) { return 1.f / (1.f + expf(-x)); }

// ---------------- K0: reset grid barrier ----------------
__global__ void k_reset() { g_bar = 0u; }

// ---------------- K1: attention softmax (h-term is a scalar shift -> a,c constant over t) ----
__global__ void k_attn(const int* __restrict__ diag, const int* __restrict__ proc,
                       const int* __restrict__ med, const float* __restrict__ enc,
                       const float* __restrict__ aw, const float* __restrict__ ab) {
    __shared__ float ss[320];
    int tid = threadIdx.x, lane = tid & 31, w = tid >> 5;
    for (int rr = 0; rr < 40; rr++) {
        int r = w + 8 * rr;                       // 8 warps x 40 rows = 320
        int idx = (r < 128) ? diag[r] : ((r < 192) ? proc[r - 128] : med[r - 192]);
        const float* row = enc + (size_t)idx * EDIM;
        float acc = 0.f;
        for (int k = lane; k < EDIM; k += 32) acc += row[k] * aw[EDIM + k];
        #pragma unroll
        for (int o = 16; o; o >>= 1) acc += __shfl_xor_sync(~0u, acc, o);
        if (!lane) ss[r] = acc + ab[0];
    }
    __syncthreads();
    if (w == 0) {
        float mx = -1e30f;
        for (int r = lane; r < 320; r += 32) mx = fmaxf(mx, ss[r]);
        #pragma unroll
        for (int o = 16; o; o >>= 1) mx = fmaxf(mx, __shfl_xor_sync(~0u, mx, o));
        float s = 0.f;
        for (int r = lane; r < 320; r += 32) { float e = expf(ss[r] - mx); ss[r] = e; s += e; }
        #pragma unroll
        for (int o = 16; o; o >>= 1) s += __shfl_xor_sync(~0u, s, o);
        float inv = 1.f / s;
        for (int r = lane; r < 320; r += 32) g_a[r] = ss[r] * inv;
    }
}

// ---------------- K2: c = a@ctx, h0 init, Hb pad column zero ----------------
__global__ void k_ctx(const int* __restrict__ diag, const int* __restrict__ proc,
                      const int* __restrict__ med, const float* __restrict__ enc,
                      const float* __restrict__ dec_emb) {
    __shared__ float sa[320];
    __shared__ int   si[320];
    int tid = threadIdx.x;
    int k = blockIdx.x * 256 + tid;
    for (int i = tid; i < 320; i += 256) {
        sa[i] = g_a[i];
        si[i] = (i < 128) ? diag[i] : ((i < 192) ? proc[i - 128] : med[i - 192]);
    }
    __syncthreads();
    float a0 = 0.f, a1 = 0.f, a2 = 0.f, a3 = 0.f;
    for (int i = 0; i < 320; i += 4) {
        a0 += sa[i + 0] * enc[(size_t)si[i + 0] * EDIM + k];
        a1 += sa[i + 1] * enc[(size_t)si[i + 1] * EDIM + k];
        a2 += sa[i + 2] * enc[(size_t)si[i + 2] * EDIM + k];
        a3 += sa[i + 3] * enc[(size_t)si[i + 3] * EDIM + k];
    }
    g_c[k] = (a0 + a1) + (a2 + a3);
    g_h2[0][k] = dec_emb[(size_t)V0 * EDIM + k];
    g_Hb[(size_t)k * TPAD + TSTEP] = 0.f;           // pad column for paired reads in k_out
}

// ---------------- K2b: gib[j] = W_ih[j, :E]@c + b_ih[j]  (grid 384 x 8 warps) ---------------
__global__ void k_gib(const float* __restrict__ wih, const float* __restrict__ bih) {
    __shared__ float cs[EDIM];
    int tid = threadIdx.x, lane = tid & 31, w = tid >> 5;
    for (int k = tid; k < EDIM; k += 256) cs[k] = g_c[k];
    __syncthreads();
    int j = blockIdx.x * 8 + w;
    const float* row = wih + (size_t)j * 2048;      // c-part = first E columns
    float acc = 0.f;
    #pragma unroll 8
    for (int m = 0; m < 32; m++) acc += row[m * 32 + lane] * cs[m * 32 + lane];
    #pragma unroll
    for (int o = 16; o; o >>= 1) acc += __shfl_xor_sync(~0u, acc, o);
    if (!lane) g_gib[j] = acc + bih[j];
}

// ---------------- K3: gi[t][j] = W_ih[j, E:]@x_t + gib[j]   (3072 x 65 x 1024 GEMM) ---------
__global__ void __launch_bounds__(256) k_gix(const float* __restrict__ wih,
                                             const float* __restrict__ dec_emb,
                                             const int* __restrict__ dec_tok) {
    __shared__ __align__(16) float wsm[32 * 33];    // [kk][jl], pad 33 -> conflict-free
    __shared__ __align__(16) float xs[32 * HSW];    // [kk][t], zero-padded t>=65
    __shared__ int tok[TSTEP];
    int tid = threadIdx.x;
    int tj = tid & 31, tt = tid >> 5;               // lane = j-within-tile, warp = t-phase
    int j0 = blockIdx.x * 32, j = j0 + tj;
    if (tid < TSTEP) tok[tid] = tid ? dec_tok[tid - 1] : V0;

    ull acc[5];
    #pragma unroll
    for (int m = 0; m < 5; m++) acc[m] = 0ull;
    bool ext = (tt == 0);                           // warp 0 owns the extra pair tp=32 (t=64,65)

    for (int k0 = 0; k0 < EDIM; k0 += 32) {
        __syncthreads();
        for (int idx = tid; idx < 1024; idx += 256) {   // W tile (x-part of W_ih)
            int jl = idx >> 5, kk = idx & 31;
            wsm[kk * 33 + jl] = wih[(size_t)(j0 + jl) * 2048 + 1024 + k0 + kk];
        }
        for (int idx = tid; idx < 32 * HSW; idx += 256) { // X tile (kk fast -> coalesced gather)
            int kk = idx & 31, t = idx >> 5;
            xs[kk * HSW + t] = (t < TSTEP) ? dec_emb[(size_t)tok[t] * EDIM + k0 + kk] : 0.f;
        }
        __syncthreads();
        #pragma unroll 4
        for (int kk = 0; kk < 32; kk++) {
            float wv = wsm[kk * 33 + tj];
            ull w2 = pk2(wv, wv);
            const ull* hp = (const ull*)(xs + kk * HSW);
            #pragma unroll
            for (int m = 0; m < 4; m++) acc[m] = ffma2(w2, hp[tt + 8 * m], acc[m]);
            if (ext) acc[4] = ffma2(w2, hp[32], acc[4]);
        }
    }
    float gb = g_gib[j];
    int mlim = ext ? 5 : 4;
    for (int m = 0; m < mlim; m++) {
        int t0 = 2 * (tt + 8 * m);
        float x, y; upk2(acc[m], x, y);
        g_gi[(size_t)t0 * R3 + j] = x + gb;
        g_gi[(size_t)(t0 + 1) * R3 + j] = y + gb;   // t=65 lands in pad row, never read
    }
}

// ---------------- K4: persistent GRU recurrence (grid=128, double-buffered h) ----------------
__global__ void __launch_bounds__(256, 1) k_rec(const float* __restrict__ whh,
                                                const float* __restrict__ bhh) {
    __shared__ __align__(16) float hs[EDIM];
    int tid = threadIdx.x, lane = tid & 31, w = tid >> 5;
    int i = blockIdx.x * 8 + w;                     // this warp's hidden index (0..1023)

    // register-resident W_hh rows {i, E+i, 2E+i} as f32x2: 48 x u64
    const ull* Wu = (const ull*)whh;
    ull wr[16], wz[16], wn[16];
    #pragma unroll
    for (int q = 0; q < 16; q++) {
        wr[q] = Wu[(size_t)i * 512 + q * 32 + lane];
        wz[q] = Wu[(size_t)(EDIM + i) * 512 + q * 32 + lane];
        wn[q] = Wu[(size_t)(2 * EDIM + i) * 512 + q * 32 + lane];
    }
    float bhr = 0.f, bhz = 0.f, bhn = 0.f;
    if (!lane) { bhr = bhh[i]; bhz = bhh[EDIM + i]; bhn = bhh[2 * EDIM + i]; }

    for (int t = 0; t < TSTEP; t++) {
        const float* hrd = g_h2[t & 1];
        float*       hwr = g_h2[(t + 1) & 1];

        // prefetch gi (independent of h; overlaps with h load)
        float gir = 0.f, giz = 0.f, gin = 0.f;
        if (!lane) {
            const float* gp = g_gi + (size_t)t * R3 + i;
            gir = __ldcg(gp); giz = __ldcg(gp + EDIM); gin = __ldcg(gp + 2 * EDIM);
        }
        // stage h from L2 (fresh: prior step's writes ordered by fenced grid barrier)
        const float2* s = (const float2*)hrd;
        float2 a0 = __ldcg(s + tid), a1 = __ldcg(s + 256 + tid);
        ((float2*)hs)[tid] = a0; ((float2*)hs)[256 + tid] = a1;
        __syncthreads();

        ull ar = 0ull, az = 0ull, an = 0ull;
        const ull* h2 = (const ull*)hs;
        #pragma unroll
        for (int q = 0; q < 16; q++) {
            ull h = h2[q * 32 + lane];
            ar = ffma2(wr[q], h, ar);
            az = ffma2(wz[q], h, az);
            an = ffma2(wn[q], h, an);
        }
        float x, y, sr, sz, sn;
        upk2(ar, x, y); sr = x + y;
        upk2(az, x, y); sz = x + y;
        upk2(an, x, y); sn = x + y;
        #pragma unroll
        for (int o = 16; o; o >>= 1) {
            sr += __shfl_xor_sync(~0u, sr, o);
            sz += __shfl_xor_sync(~0u, sz, o);
            sn += __shfl_xor_sync(~0u, sn, o);
        }
        if (!lane) {
            float r = sigf(gir + sr + bhr);
            float z = sigf(giz + sz + bhz);
            float n = tanhf(gin + r * (sn + bhn));
            float hn = (1.f - z) * n + z * hs[i];
            __stcg(hwr + i, hn);
            g_Hb[(size_t)i * TPAD + t] = fmaxf(hn, 0.f);
        }
        if (t < TSTEP - 1) {
            __threadfence();                         // EVERY thread fences its own writes
            __syncthreads();                         // block done: stores fenced, hs reads done
            if (tid == 0) {
                atomicAdd(&g_bar, 1u);
                unsigned tgt = (unsigned)GBLK * (unsigned)(t + 1);
                while (*(volatile unsigned*)&g_bar < tgt) { }
                __threadfence();                     // acquire side
            }
            __syncthreads();
        }
    }
}

// ---------------- K5: logits[t][v] = out_w[v]@relu(h_t) + out_b[v]  (32002x66x1024) ---------
// 128 v per block (4 cols/thread), duplicated-f32x2 weights in smem -> no pk2, fewer w-LDS.
__global__ void __launch_bounds__(256) k_out(const float* __restrict__ ow,
                                             const float* __restrict__ ob,
                                             float* __restrict__ out) {
    __shared__ __align__(16) float2 ws2[16 * 130];  // [kk][vl] (dup'd), row pad 130
    __shared__ __align__(16) float hsx[16 * HSW];   // [kk][t], zero-padded
    int tid = threadIdx.x;
    int tv = tid & 31, tt = tid >> 5;
    int v0 = blockIdx.x * 128;
    bool ext = (tt == 0);

    ull acc[4][5];
    #pragma unroll
    for (int c = 0; c < 4; c++)
        #pragma unroll
        for (int m = 0; m < 5; m++) acc[c][m] = 0ull;

    for (int k0 = 0; k0 < EDIM; k0 += 16) {
        __syncthreads();
        for (int idx = tid; idx < 2048; idx += 256) {   // W tile (kk fast -> coalesced gmem)
            int kk = idx & 15, vl = idx >> 4;
            int v = v0 + vl;
            float wv = (v < VOUT) ? ow[(size_t)v * EDIM + k0 + kk] : 0.f;
            ws2[kk * 130 + vl] = make_float2(wv, wv);
        }
        for (int idx = tid; idx < 16 * HSW; idx += 256) { // H tile (t fast -> coalesced gmem)
            int kk = idx / HSW, t = idx % HSW;
            hsx[kk * HSW + t] = (t < TPAD) ? g_Hb[(size_t)(k0 + kk) * TPAD + t] : 0.f;
        }
        __syncthreads();
        #pragma unroll 2
        for (int kk = 0; kk < 16; kk++) {
            const ull* hp = (const ull*)(hsx + kk * HSW);
            const ull* wp = (const ull*)(ws2 + kk * 130);
            ull w2[4];
            #pragma unroll
            for (int c = 0; c < 4; c++) w2[c] = wp[c * 32 + tv];
            #pragma unroll
            for (int m = 0; m < 4; m++) {
                ull h = hp[tt + 8 * m];                  // warp-broadcast, conflict-free
                #pragma unroll
                for (int c = 0; c < 4; c++) acc[c][m] = ffma2(w2[c], h, acc[c][m]);
            }
            if (ext) {
                ull h = hp[32];
                #pragma unroll
                for (int c = 0; c < 4; c++) acc[c][4] = ffma2(w2[c], h, acc[c][4]);
            }
        }
    }
    int mlim = ext ? 5 : 4;
    #pragma unroll
    for (int c = 0; c < 4; c++) {
        int v = v0 + c * 32 + tv;
        if (v >= VOUT) continue;
        float bias = ob[v];
        for (int m = 0; m < mlim; m++) {
            int t0 = 2 * (tt + 8 * m);
            float x, y; upk2(acc[c][m], x, y);
            out[(size_t)t0 * VOUT + v] = x + bias;
            if (t0 + 1 < TSTEP) out[(size_t)(t0 + 1) * VOUT + v] = y + bias;
        }
    }
}

// ---------------- launch ----------------
extern "C" void kernel_launch(void* const* d_in, const int* in_sizes, int n_in,
                              void* d_out, int out_size) {
    const int*   diag    = (const int*)  d_in[0];
    const int*   proc    = (const int*)  d_in[1];
    const int*   med     = (const int*)  d_in[2];
    const int*   dec_tok = (const int*)  d_in[3];
    const float* enc     = (const float*)d_in[4];
    const float* dec_emb = (const float*)d_in[5];
    const float* attn_w  = (const float*)d_in[6];
    const float* attn_b  = (const float*)d_in[7];
    const float* wih     = (const float*)d_in[8];
    const float* whh     = (const float*)d_in[9];
    const float* bih     = (const float*)d_in[10];
    const float* bhh     = (const float*)d_in[11];
    const float* outw    = (const float*)d_in[12];
    const float* outb    = (const float*)d_in[13];
    float* out = (float*)d_out;

    k_reset<<<1, 1>>>();
    k_attn <<<1, 256>>>(diag, proc, med, enc, attn_w, attn_b);
    k_ctx  <<<4, 256>>>(diag, proc, med, enc, dec_emb);
    k_gib  <<<R3 / 8, 256>>>(wih, bih);
    k_gix  <<<R3 / 32, 256>>>(wih, dec_emb, dec_tok);
    k_rec  <<<GBLK, 256>>>(whh, bhh);
    k_out  <<<(VOUT + 127) / 128, 256>>>(outw, outb, out);
}

// round 15
// speedup vs baseline: 1.2205x; 1.2205x over previous
#include <cuda_runtime.h>

#define V0    32000
#define EDIM  1024
#define TSTEP 65
#define TPAD  66
#define R3    3072
#define VOUT  32002
#define GBLK  128     // persistent recurrence blocks (<=148 SMs -> all co-resident)
#define HSW   70      // padded t-width in shared (even -> 8B-aligned rows)

typedef unsigned long long ull;

// ---------------- scratch (__device__ globals; no allocs allowed) ----------------
__device__ __align__(16) float g_a[320];          // exp(score) (unnormalized)
__device__ __align__(16) float g_apart[10];       // per-block partial sums of exp
__device__ __align__(16) float g_c[EDIM];
__device__ __align__(16) float g_gib[R3];
__device__ __align__(16) float g_gi[TPAD * R3];   // gi[t][j], t=65 is pad
__device__ __align__(16) float g_h2[2][EDIM];     // double-buffered hidden state
__device__ __align__(16) float g_Hb[EDIM * TPAD]; // relu(h_t), [k][t], col t=65 = 0
__device__ __align__(128) unsigned int g_bars[64 * 32];  // one counter per step, 128B apart

// ---------------- f32x2 + scoped-atomic helpers ----------------
__device__ __forceinline__ ull pk2(float x, float y) {
    ull r; asm("mov.b64 %0,{%1,%2};" : "=l"(r) : "f"(x), "f"(y)); return r;
}
__device__ __forceinline__ void upk2(ull p, float &x, float &y) {
    asm("mov.b64 {%0,%1},%2;" : "=f"(x), "=f"(y) : "l"(p));
}
__device__ __forceinline__ ull ffma2(ull a, ull b, ull c) {
    ull d; asm("fma.rn.f32x2 %0,%1,%2,%3;" : "=l"(d) : "l"(a), "l"(b), "l"(c)); return d;
}
__device__ __forceinline__ float sigf(float x) { return 1.f / (1.f + expf(-x)); }

__device__ __forceinline__ float2 ldg_rlx2(const float2* p) {
    float2 v;
    asm volatile("ld.relaxed.gpu.global.v2.f32 {%0,%1},[%2];"
                 : "=f"(v.x), "=f"(v.y) : "l"(p) : "memory");
    return v;
}
__device__ __forceinline__ void stg_rlx(float* p, float v) {
    asm volatile("st.relaxed.gpu.global.f32 [%0],%1;" :: "l"(p), "f"(v) : "memory");
}
__device__ __forceinline__ void bar_arrive(unsigned* p) {
    asm volatile("red.release.gpu.global.add.u32 [%0],1;" :: "l"(p) : "memory");
}
__device__ __forceinline__ unsigned ld_acq(const unsigned* p) {
    unsigned v;
    asm volatile("ld.acquire.gpu.global.u32 %0,[%1];" : "=r"(v) : "l"(p) : "memory");
    return v;
}

// ---------------- K1: attention exp(scores) + barrier reset (fused) ----------------
// softmax shift-invariance: the h.w_h term is a scalar shift -> a,c constant over all steps.
// scores ~ N(0, ~0.013): exp without max-subtraction is exact w.r.t. softmax.
__global__ void __launch_bounds__(1024) k_attn(const int* __restrict__ diag,
                                               const int* __restrict__ proc,
                                               const int* __restrict__ med,
                                               const float* __restrict__ enc,
                                               const float* __restrict__ aw,
                                               const float* __restrict__ ab) {
    __shared__ float we[EDIM];
    __shared__ float wsum[32];
    int tid = threadIdx.x, lane = tid & 31, w = tid >> 5;
    if (blockIdx.x == 0 && tid < 64) g_bars[tid * 32] = 0u;   // reset k_rec step barriers
    we[tid] = aw[EDIM + tid];
    __syncthreads();
    int r = blockIdx.x * 32 + w;                  // 10 blocks x 32 warps = 320 rows
    int idx = (r < 128) ? diag[r] : ((r < 192) ? proc[r - 128] : med[r - 192]);
    const float* row = enc + (size_t)idx * EDIM;
    float acc = 0.f;
    #pragma unroll
    for (int m = 0; m < 32; m++) acc += row[m * 32 + lane] * we[m * 32 + lane];
    #pragma unroll
    for (int o = 16; o; o >>= 1) acc += __shfl_xor_sync(~0u, acc, o);
    if (!lane) {
        float e = expf(acc + ab[0]);
        g_a[r] = e;
        wsum[w] = e;
    }
    __syncthreads();
    if (w == 0) {                                  // deterministic block-partial reduction
        float s = wsum[lane];
        #pragma unroll
        for (int o = 16; o; o >>= 1) s += __shfl_xor_sync(~0u, s, o);
        if (!lane) g_apart[blockIdx.x] = s;
    }
}

// ---------------- K2: c = (a/sum)@ctx, h0 init, Hb pad column zero ----------------
__global__ void k_ctx(const int* __restrict__ diag, const int* __restrict__ proc,
                      const int* __restrict__ med, const float* __restrict__ enc,
                      const float* __restrict__ dec_emb) {
    __shared__ float sa[320];
    __shared__ int   si[320];
    int tid = threadIdx.x;
    int k = blockIdx.x * 256 + tid;
    float s = 0.f;
    #pragma unroll
    for (int b = 0; b < 10; b++) s += g_apart[b];   // fixed order -> deterministic
    float inv = 1.f / s;
    for (int i = tid; i < 320; i += 256) {
        sa[i] = g_a[i] * inv;
        si[i] = (i < 128) ? diag[i] : ((i < 192) ? proc[i - 128] : med[i - 192]);
    }
    __syncthreads();
    float a0 = 0.f, a1 = 0.f, a2 = 0.f, a3 = 0.f;
    for (int i = 0; i < 320; i += 4) {
        a0 += sa[i + 0] * enc[(size_t)si[i + 0] * EDIM + k];
        a1 += sa[i + 1] * enc[(size_t)si[i + 1] * EDIM + k];
        a2 += sa[i + 2] * enc[(size_t)si[i + 2] * EDIM + k];
        a3 += sa[i + 3] * enc[(size_t)si[i + 3] * EDIM + k];
    }
    g_c[k] = (a0 + a1) + (a2 + a3);
    g_h2[0][k] = dec_emb[(size_t)V0 * EDIM + k];
    g_Hb[(size_t)k * TPAD + TSTEP] = 0.f;           // pad column for paired reads in k_out
}

// ---------------- K2b: gib[j] = W_ih[j, :E]@c + b_ih[j] ----------------
__global__ void k_gib(const float* __restrict__ wih, const float* __restrict__ bih) {
    __shared__ float cs[EDIM];
    int tid = threadIdx.x, lane = tid & 31, w = tid >> 5;
    for (int k = tid; k < EDIM; k += 256) cs[k] = g_c[k];
    __syncthreads();
    int j = blockIdx.x * 8 + w;
    const float* row = wih + (size_t)j * 2048;      // c-part = first E columns
    float acc = 0.f;
    #pragma unroll
    for (int m = 0; m < 32; m++) acc += row[m * 32 + lane] * cs[m * 32 + lane];
    #pragma unroll
    for (int o = 16; o; o >>= 1) acc += __shfl_xor_sync(~0u, acc, o);
    if (!lane) g_gib[j] = acc + bih[j];
}

// ---------------- K3: gi[t][j] = W_ih[j, E:]@x_t + gib[j]   (3072 x 65 x 1024) -------------
__global__ void __launch_bounds__(256) k_gix(const float* __restrict__ wih,
                                             const float* __restrict__ dec_emb,
                                             const int* __restrict__ dec_tok) {
    __shared__ __align__(16) float wsm[32 * 33];    // [kk][jl], pad 33 -> conflict-free
    __shared__ __align__(16) float xs[32 * HSW];    // [kk][t], zero-padded t>=65
    __shared__ int tok[TSTEP];
    int tid = threadIdx.x;
    int tj = tid & 31, tt = tid >> 5;
    int j0 = blockIdx.x * 32, j = j0 + tj;
    if (tid < TSTEP) tok[tid] = tid ? dec_tok[tid - 1] : V0;

    ull acc[5];
    #pragma unroll
    for (int m = 0; m < 5; m++) acc[m] = 0ull;
    bool ext = (tt == 0);                           // warp 0 owns extra pair (t=64,65)

    for (int k0 = 0; k0 < EDIM; k0 += 32) {
        __syncthreads();
        for (int idx = tid; idx < 1024; idx += 256) {
            int jl = idx >> 5, kk = idx & 31;
            wsm[kk * 33 + jl] = wih[(size_t)(j0 + jl) * 2048 + 1024 + k0 + kk];
        }
        for (int idx = tid; idx < 32 * HSW; idx += 256) {
            int kk = idx & 31, t = idx >> 5;
            xs[kk * HSW + t] = (t < TSTEP) ? dec_emb[(size_t)tok[t] * EDIM + k0 + kk] : 0.f;
        }
        __syncthreads();
        #pragma unroll 4
        for (int kk = 0; kk < 32; kk++) {
            float wv = wsm[kk * 33 + tj];
            ull w2 = pk2(wv, wv);
            const ull* hp = (const ull*)(xs + kk * HSW);
            #pragma unroll
            for (int m = 0; m < 4; m++) acc[m] = ffma2(w2, hp[tt + 8 * m], acc[m]);
            if (ext) acc[4] = ffma2(w2, hp[32], acc[4]);
        }
    }
    float gb = g_gib[j];
    int mlim = ext ? 5 : 4;
    for (int m = 0; m < mlim; m++) {
        int t0 = 2 * (tt + 8 * m);
        float x, y; upk2(acc[m], x, y);
        g_gi[(size_t)t0 * R3 + j] = x + gb;
        g_gi[(size_t)(t0 + 1) * R3 + j] = y + gb;   // t=65 -> pad row, never read
    }
}

// ---------------- K4: persistent GRU recurrence (scoped-atomic grid barrier) ----------------
__global__ void __launch_bounds__(256, 1) k_rec(const float* __restrict__ whh,
                                                const float* __restrict__ bhh) {
    __shared__ __align__(16) float hs[EDIM];
    int tid = threadIdx.x, lane = tid & 31, w = tid >> 5;
    int i = blockIdx.x * 8 + w;                     // this warp's hidden index

    // register-resident W_hh rows {i, E+i, 2E+i} as f32x2: 48 x u64
    const ull* Wu = (const ull*)whh;
    ull wr[16], wz[16], wn[16];
    #pragma unroll
    for (int q = 0; q < 16; q++) {
        wr[q] = Wu[(size_t)i * 512 + q * 32 + lane];
        wz[q] = Wu[(size_t)(EDIM + i) * 512 + q * 32 + lane];
        wn[q] = Wu[(size_t)(2 * EDIM + i) * 512 + q * 32 + lane];
    }
    float bhr = 0.f, bhz = 0.f, bhn = 0.f;
    float gir = 0.f, giz = 0.f, gin = 0.f;
    if (!lane) {
        bhr = bhh[i]; bhz = bhh[EDIM + i]; bhn = bhh[2 * EDIM + i];
        const float* gp = g_gi + i;                 // gi for t=0
        gir = __ldcg(gp); giz = __ldcg(gp + EDIM); gin = __ldcg(gp + 2 * EDIM);
    }

    for (int t = 0; t < TSTEP; t++) {
        const float2* s = (const float2*)g_h2[t & 1];
        float*        hwr = g_h2[(t + 1) & 1];

        // stage h (strong gpu-scope loads; freshness via acquire barrier chain)
        float2 a0 = ldg_rlx2(s + tid), a1 = ldg_rlx2(s + 256 + tid);
        ((float2*)hs)[tid] = a0; ((float2*)hs)[256 + tid] = a1;
        __syncthreads();

        ull ar0 = 0ull, ar1 = 0ull, az0 = 0ull, az1 = 0ull, an0 = 0ull, an1 = 0ull;
        const ull* h2 = (const ull*)hs;
        #pragma unroll
        for (int q = 0; q < 16; q += 2) {           // 2-way split chains (dep depth 8)
            ull ha = h2[q * 32 + lane], hb = h2[(q + 1) * 32 + lane];
            ar0 = ffma2(wr[q], ha, ar0); ar1 = ffma2(wr[q + 1], hb, ar1);
            az0 = ffma2(wz[q], ha, az0); az1 = ffma2(wz[q + 1], hb, az1);
            an0 = ffma2(wn[q], ha, an0); an1 = ffma2(wn[q + 1], hb, an1);
        }
        float x0, y0, x1, y1, sr, sz, sn;
        upk2(ar0, x0, y0); upk2(ar1, x1, y1); sr = (x0 + y0) + (x1 + y1);
        upk2(az0, x0, y0); upk2(az1, x1, y1); sz = (x0 + y0) + (x1 + y1);
        upk2(an0, x0, y0); upk2(an1, x1, y1); sn = (x0 + y0) + (x1 + y1);
        #pragma unroll
        for (int o = 16; o; o >>= 1) {
            sr += __shfl_xor_sync(~0u, sr, o);
            sz += __shfl_xor_sync(~0u, sz, o);
            sn += __shfl_xor_sync(~0u, sn, o);
        }
        if (!lane) {
            float r = sigf(gir + sr + bhr);
            float z = sigf(giz + sz + bhz);
            float n = tanhf(gin + r * (sn + bhn));
            float hn = (1.f - z) * n + z * hs[i];
            stg_rlx(hwr + i, hn);                   // strong gpu-scope store, no fence needed
            g_Hb[(size_t)i * TPAD + t] = fmaxf(hn, 0.f);
            if (t + 1 < TSTEP) {                    // prefetch next gi while barrier spins
                const float* gp = g_gi + (size_t)(t + 1) * R3 + i;
                gir = __ldcg(gp); giz = __ldcg(gp + EDIM); gin = __ldcg(gp + 2 * EDIM);
            }
        }
        if (t < TSTEP - 1) {
            __syncthreads();                        // all h stores HB-before arrival
            if (tid == 0) {
                unsigned* bar = &g_bars[t * 32];
                bar_arrive(bar);                    // red.release.gpu (fire & forget)
                if (ld_acq(bar) < GBLK) {           // fast path: already complete
                    while (ld_acq(bar) < GBLK) __nanosleep(64);  // backoff: don't throttle LTS
                }
            }
            __syncthreads();
        }
    }
}

// ---------------- K5: logits = out_w @ relu(H) + out_b  (32002 x 65 x 1024) ----------------
__global__ void __launch_bounds__(256) k_out(const float* __restrict__ ow,
                                             const float* __restrict__ ob,
                                             float* __restrict__ out) {
    __shared__ __align__(16) float2 ws2[16 * 130];  // [kk][vl] (duplicated), row pad 130
    __shared__ __align__(16) float hsx[16 * HSW];   // [kk][t], zero-padded
    int tid = threadIdx.x;
    int tv = tid & 31, tt = tid >> 5;
    int v0 = blockIdx.x * 128;
    bool ext = (tt == 0);

    ull acc[4][5];
    #pragma unroll
    for (int c = 0; c < 4; c++)
        #pragma unroll
        for (int m = 0; m < 5; m++) acc[c][m] = 0ull;

    for (int k0 = 0; k0 < EDIM; k0 += 16) {
        __syncthreads();
        for (int idx = tid; idx < 2048; idx += 256) {
            int kk = idx & 15, vl = idx >> 4;
            int v = v0 + vl;
            float wv = (v < VOUT) ? ow[(size_t)v * EDIM + k0 + kk] : 0.f;
            ws2[kk * 130 + vl] = make_float2(wv, wv);
        }
        for (int idx = tid; idx < 16 * HSW; idx += 256) {
            int kk = idx / HSW, t = idx % HSW;
            hsx[kk * HSW + t] = (t < TPAD) ? g_Hb[(size_t)(k0 + kk) * TPAD + t] : 0.f;
        }
        __syncthreads();
        #pragma unroll 2
        for (int kk = 0; kk < 16; kk++) {
            const ull* hp = (const ull*)(hsx + kk * HSW);
            const ull* wp = (const ull*)(ws2 + kk * 130);
            ull w2[4];
            #pragma unroll
            for (int c = 0; c < 4; c++) w2[c] = wp[c * 32 + tv];
            #pragma unroll
            for (int m = 0; m < 4; m++) {
                ull h = hp[tt + 8 * m];             // warp-broadcast, conflict-free
                #pragma unroll
                for (int c = 0; c < 4; c++) acc[c][m] = ffma2(w2[c], h, acc[c][m]);
            }
            if (ext) {
                ull h = hp[32];
                #pragma unroll
                for (int c = 0; c < 4; c++) acc[c][4] = ffma2(w2[c], h, acc[c][4]);
            }
        }
    }
    int mlim = ext ? 5 : 4;
    #pragma unroll
    for (int c = 0; c < 4; c++) {
        int v = v0 + c * 32 + tv;
        if (v >= VOUT) continue;
        float bias = ob[v];
        for (int m = 0; m < mlim; m++) {
            int t0 = 2 * (tt + 8 * m);
            float x, y; upk2(acc[c][m], x, y);
            out[(size_t)t0 * VOUT + v] = x + bias;
            if (t0 + 1 < TSTEP) out[(size_t)(t0 + 1) * VOUT + v] = y + bias;
        }
    }
}

// ---------------- launch ----------------
extern "C" void kernel_launch(void* const* d_in, const int* in_sizes, int n_in,
                              void* d_out, int out_size) {
    const int*   diag    = (const int*)  d_in[0];
    const int*   proc    = (const int*)  d_in[1];
    const int*   med     = (const int*)  d_in[2];
    const int*   dec_tok = (const int*)  d_in[3];
    const float* enc     = (const float*)d_in[4];
    const float* dec_emb = (const float*)d_in[5];
    const float* attn_w  = (const float*)d_in[6];
    const float* attn_b  = (const float*)d_in[7];
    const float* wih     = (const float*)d_in[8];
    const float* whh     = (const float*)d_in[9];
    const float* bih     = (const float*)d_in[10];
    const float* bhh     = (const float*)d_in[11];
    const float* outw    = (const float*)d_in[12];
    const float* outb    = (const float*)d_in[13];
    float* out = (float*)d_out;

    k_attn <<<10, 1024>>>(diag, proc, med, enc, attn_w, attn_b);  // also resets barriers
    k_ctx  <<<4, 256>>>(diag, proc, med, enc, dec_emb);
    k_gib  <<<R3 / 8, 256>>>(wih, bih);
    k_gix  <<<R3 / 32, 256>>>(wih, dec_emb, dec_tok);
    k_rec  <<<GBLK, 256>>>(whh, bhh);
    k_out  <<<(VOUT + 127) / 128, 256>>>(outw, outb, out);
}